// round 10
// baseline (speedup 1.0000x reference)
#include <cuda_runtime.h>
#include <cuda_bf16.h>
#include <cuda_fp16.h>
#include <cstdint>

#define NN 50000
#define EE 400000
#define RR 3
#define DD 128
#define HH 8
#define RN (RR*NN)
#define RE (RR*EE)
#define NEG_SLOPE 0.2f
#define LN_EPS 1e-5f

// ---------------- scratch (device globals; no allocs allowed) ----------------
__device__ __align__(128) __half g_hp[(size_t)RR*NN*DD];
__device__ __align__(128) float g_el[(size_t)RN*HH];
__device__ __align__(128) float g_er[(size_t)RN*HH];
__device__ __align__(128) float g_h1[(size_t)NN*DD];
__device__ __align__(128) __nv_bfloat16 g_xh[(size_t)NN*DD];
__device__ __align__(128) __nv_bfloat16 g_xl[(size_t)NN*DD];
__device__ __align__(128) int   g_off[RN+1];
__device__ __align__(128) int   g_cnt[RN];
__device__ __align__(128) int   g_csr[RE];      // src node ids
__device__ __align__(128) int   g_bsum[256];
// pre-built B mma fragments: [slot(7)][ks(8)][n16(8)][split(2)][lane(32)][reg(4)]
__device__ __align__(128) uint32_t g_wf[7*8*8*2*32*4];

__device__ __forceinline__ uint32_t smem_u32(const void* p) {
    uint32_t a;
    asm("{ .reg .u64 t; cvta.to.shared.u64 t, %1; cvt.u32.u64 %0, t; }" : "=r"(a) : "l"(p));
    return a;
}

#define LDSM4(R, A) \
    asm volatile("ldmatrix.sync.aligned.m8n8.x4.shared.b16 {%0,%1,%2,%3}, [%4];" \
        : "=r"((R)[0]), "=r"((R)[1]), "=r"((R)[2]), "=r"((R)[3]) : "r"(A))

#define MMA(C, A, B0, B1) \
    asm volatile("mma.sync.aligned.m16n8k16.row.col.f32.bf16.bf16.f32 " \
        "{%0,%1,%2,%3}, {%4,%5,%6,%7}, {%8,%9}, {%0,%1,%2,%3};" \
        : "+f"((C)[0]), "+f"((C)[1]), "+f"((C)[2]), "+f"((C)[3]) \
        : "r"((A)[0]), "r"((A)[1]), "r"((A)[2]), "r"((A)[3]), "r"(B0), "r"(B1))

// 12 MMAs of one p-iteration, term-major: same-acc distance = 4
#define MMA_BLOCK_P(acc, ah, av, bh, bv, p) do {                 \
    MMA(acc[0][2*(p)],   ah[0], bh[0], bh[1]);                   \
    MMA(acc[0][2*(p)+1], ah[0], bh[2], bh[3]);                   \
    MMA(acc[1][2*(p)],   ah[1], bh[0], bh[1]);                   \
    MMA(acc[1][2*(p)+1], ah[1], bh[2], bh[3]);                   \
    MMA(acc[0][2*(p)],   ah[0], bv[0], bv[1]);                   \
    MMA(acc[0][2*(p)+1], ah[0], bv[2], bv[3]);                   \
    MMA(acc[1][2*(p)],   ah[1], bv[0], bv[1]);                   \
    MMA(acc[1][2*(p)+1], ah[1], bv[2], bv[3]);                   \
    MMA(acc[0][2*(p)],   av[0], bh[0], bh[1]);                   \
    MMA(acc[0][2*(p)+1], av[0], bh[2], bh[3]);                   \
    MMA(acc[1][2*(p)],   av[1], bh[0], bh[1]);                   \
    MMA(acc[1][2*(p)+1], av[1], bh[2], bh[3]);                   \
} while (0)

__device__ __forceinline__ uint32_t pack_bf16(__nv_bfloat16 a, __nv_bfloat16 b) {
    uint16_t lo = *(uint16_t*)&a, hi = *(uint16_t*)&b;
    return (uint32_t)lo | ((uint32_t)hi << 16);
}

// ---------------- setup: cnt zero + weight fragments + feat split ------------
__global__ void k_setup(const float* __restrict__ W1, const float* __restrict__ W2,
                        const float* __restrict__ Wc1, const float* __restrict__ X)
{
    int i = blockIdx.x*blockDim.x + threadIdx.x;
    if (i < RN) g_cnt[i] = 0;

    if (i < 7*8*8*32) {
        int lane = i & 31;
        int rem  = i >> 5;
        int p16  = rem & 7;  rem >>= 3;
        int ks   = rem & 7;  rem >>= 3;
        int slot = rem;
        const float* Wsrc = (slot < 3) ? W1 + (size_t)slot*16384
                          : (slot < 6) ? W2 + (size_t)(slot-3)*16384
                          : Wc1;
        uint32_t fh[4], fl[4];
        #pragma unroll
        for (int j = 0; j < 4; j++) {
            int n = p16*16 + (j>>1)*8 + (lane>>2);
            int k = ks*16  + (j&1)*8  + (lane&3)*2;
            float w0 = Wsrc[(size_t)k*128 + n];
            float w1 = Wsrc[(size_t)(k+1)*128 + n];
            __nv_bfloat16 h0 = __float2bfloat16(w0);
            __nv_bfloat16 h1 = __float2bfloat16(w1);
            __nv_bfloat16 l0 = __float2bfloat16(w0 - __bfloat162float(h0));
            __nv_bfloat16 l1 = __float2bfloat16(w1 - __bfloat162float(h1));
            fh[j] = pack_bf16(h0, h1);
            fl[j] = pack_bf16(l0, l1);
        }
        size_t base = ((((size_t)slot*8 + ks)*8 + p16)*2)*128 + (size_t)lane*4;
        *(uint4*)&g_wf[base]       = make_uint4(fh[0], fh[1], fh[2], fh[3]);
        *(uint4*)&g_wf[base + 128] = make_uint4(fl[0], fl[1], fl[2], fl[3]);
    }

    if (i < NN*16) {
        const float* xp = X + (size_t)i*8;
        float4 a = *(const float4*)xp, b = *(const float4*)(xp+4);
        float v[8] = {a.x,a.y,a.z,a.w,b.x,b.y,b.z,b.w};
        __nv_bfloat16 hh[8], ll[8];
        #pragma unroll
        for (int t = 0; t < 8; t++) {
            hh[t] = __float2bfloat16(v[t]);
            ll[t] = __float2bfloat16(v[t] - __bfloat162float(hh[t]));
        }
        *(uint4*)&g_xh[(size_t)i*8] = *(const uint4*)hh;
        *(uint4*)&g_xl[(size_t)i*8] = *(const uint4*)ll;
    }
}

// ---------------- CSR build ----------------
__global__ void k_count(const int* __restrict__ edst) {
    int i = blockIdx.x*blockDim.x + threadIdx.x;
    if (i < RE) atomicAdd(&g_cnt[(i/EE)*NN + edst[i]], 1);
}
__device__ __forceinline__ int warp_incl_scan(int v) {
    int lane = threadIdx.x & 31;
    #pragma unroll
    for (int o = 1; o < 32; o <<= 1) {
        int t = __shfl_up_sync(0xffffffffu, v, o);
        if (lane >= o) v += t;
    }
    return v;
}
__global__ void k_scan_local() {
    __shared__ int ws[32];
    int i = blockIdx.x*1024 + threadIdx.x;
    int v = (i < RN) ? g_cnt[i] : 0;
    int incl = warp_incl_scan(v);
    int lane = threadIdx.x & 31, w = threadIdx.x >> 5;
    if (lane == 31) ws[w] = incl;
    __syncthreads();
    if (w == 0) { int b = ws[lane]; b = warp_incl_scan(b); ws[lane] = b; }
    __syncthreads();
    int off = (w > 0) ? ws[w-1] : 0;
    if (i < RN) g_off[i] = off + incl - v;
    if (threadIdx.x == 0) g_bsum[blockIdx.x] = ws[31];
}
__global__ void k_scan_bsum(int nb) {
    __shared__ int ws[8];
    int v = (threadIdx.x < nb) ? g_bsum[threadIdx.x] : 0;
    int incl = warp_incl_scan(v);
    int lane = threadIdx.x & 31, w = threadIdx.x >> 5;
    if (lane == 31) ws[w] = incl;
    __syncthreads();
    if (w == 0) { int b = (lane < 8) ? ws[lane] : 0; b = warp_incl_scan(b); if (lane < 8) ws[lane] = b; }
    __syncthreads();
    int off = (w > 0) ? ws[w-1] : 0;
    if (threadIdx.x < nb) g_bsum[threadIdx.x] = off + incl - v;
}
__global__ void k_scan_add() {
    int i = blockIdx.x*1024 + threadIdx.x;
    if (i < RN) {
        int o = g_off[i] + g_bsum[blockIdx.x];
        g_off[i] = o;
        g_cnt[i] = o;
    }
    if (i == 0) g_off[RN] = RE;
}
__global__ void k_fill(const int* __restrict__ esrc, const int* __restrict__ edst) {
    int i = blockIdx.x*blockDim.x + threadIdx.x;
    if (i < RE) {
        int idx = (i/EE)*NN + edst[i];
        int p = atomicAdd(&g_cnt[idx], 1);
        g_csr[p] = esrc[i];
    }
}

// ---------------- projection GEMM: A smem full-K, B direct-LDG fragments ----
#define ASTRA 136
#define SM_PROJ (2*128*ASTRA*2 + 1024)
#define SM_CLS  (2*128*ASTRA*2 + 2048)

__global__ void __launch_bounds__(256, 2)
k_proj(int slot0, const float* __restrict__ al, const float* __restrict__ ar)
{
    extern __shared__ char smem[];
    __nv_bfloat16* Ah = (__nv_bfloat16*)smem;       // [128][136]
    __nv_bfloat16* Av = Ah + 128*ASTRA;
    float* Ps = (float*)(Av + 128*ASTRA);

    const int tid  = threadIdx.x;
    const int lane = tid & 31;
    const int w    = tid >> 5;
    const int wm   = w & 3;
    const int wn   = w >> 2;
    const int r    = blockIdx.y;
    const int slot = slot0 + r;
    const int n0   = blockIdx.x * 128;

    Ps[tid] = (tid < 128) ? al[r*128 + tid] : ar[r*128 + tid - 128];

    #pragma unroll
    for (int i = 0; i < 8; i++) {
        int idx = tid + i*256;
        int m = idx >> 4, k = (idx & 15) << 3;
        int gm = n0 + m;
        uint4 zh = make_uint4(0,0,0,0), zl = zh;
        if (gm < NN) {
            zh = *(const uint4*)&g_xh[(size_t)gm*128 + k];
            zl = *(const uint4*)&g_xl[(size_t)gm*128 + k];
        }
        *(uint4*)&Ah[m*ASTRA + k] = zh;
        *(uint4*)&Av[m*ASTRA + k] = zl;
    }
    __syncthreads();

    const uint32_t sAh = smem_u32(Ah), sAv = smem_u32(Av);
    const uint32_t aOff = ((wm*32 + (lane & 15))*ASTRA + (lane >> 4)*8) * 2;
    const uint32_t* wf = g_wf + (size_t)slot*8*8*2*128;

    float acc[2][8][4];
    #pragma unroll
    for (int mt = 0; mt < 2; mt++)
        #pragma unroll
        for (int nt = 0; nt < 8; nt++)
            #pragma unroll
            for (int q = 0; q < 4; q++) acc[mt][nt][q] = 0.f;

    #pragma unroll 2
    for (int ks = 0; ks < 8; ks++) {
        uint32_t ah[2][4], av[2][4];
        #pragma unroll
        for (int mt = 0; mt < 2; mt++) {
            LDSM4(ah[mt], sAh + aOff + mt*(16*ASTRA*2) + ks*32);
            LDSM4(av[mt], sAv + aOff + mt*(16*ASTRA*2) + ks*32);
        }
        #pragma unroll
        for (int p = 0; p < 4; p++) {
            int p16 = wn*4 + p;
            const uint4* bp = (const uint4*)(wf + ((ks*8 + p16)*2)*128) + lane;
            uint4 h4 = __ldg(bp);
            uint4 l4 = __ldg(bp + 32);
            uint32_t bh[4] = {h4.x, h4.y, h4.z, h4.w};
            uint32_t bv[4] = {l4.x, l4.y, l4.z, l4.w};
            MMA_BLOCK_P(acc, ah, av, bh, bv, p);
        }
    }

    const int g  = lane >> 2;
    const int c2 = (lane & 3) * 2;
    #pragma unroll
    for (int mt = 0; mt < 2; mt++) {
        #pragma unroll
        for (int rh = 0; rh < 2; rh++) {
            int gm = n0 + wm*32 + mt*16 + rh*8 + g;
            bool ok = gm < NN;
            if (ok) {
                __half* op = g_hp + ((size_t)r*NN + gm)*128;
                #pragma unroll
                for (int nt = 0; nt < 8; nt++) {
                    int n = wn*64 + nt*8 + c2;
                    *(__half2*)&op[n] =
                        __floats2half2_rn(acc[mt][nt][rh*2], acc[mt][nt][rh*2+1]);
                }
            }
            #pragma unroll
            for (int j = 0; j < 4; j++) {
                float el = 0.f, er = 0.f;
                #pragma unroll
                for (int t = 0; t < 2; t++) {
                    int nt = 2*j + t;
                    int n = wn*64 + nt*8 + c2;
                    float v0 = acc[mt][nt][rh*2], v1 = acc[mt][nt][rh*2+1];
                    el += v0*Ps[n] + v1*Ps[n+1];
                    er += v0*Ps[128+n] + v1*Ps[128+n+1];
                }
                el += __shfl_xor_sync(0xffffffffu, el, 1);
                er += __shfl_xor_sync(0xffffffffu, er, 1);
                el += __shfl_xor_sync(0xffffffffu, el, 2);
                er += __shfl_xor_sync(0xffffffffu, er, 2);
                if ((lane & 3) == 0 && ok) {
                    g_el[((size_t)r*NN + gm)*HH + wn*4 + j] = el;
                    g_er[((size_t)r*NN + gm)*HH + wn*4 + j] = er;
                }
            }
        }
    }
}

// ---------------- classifier GEMM ----------------
__global__ void __launch_bounds__(256, 2)
k_cls(const float* __restrict__ bc1, const float* __restrict__ wc2,
      const float* __restrict__ bc2, float* __restrict__ out1)
{
    extern __shared__ char smem[];
    __nv_bfloat16* Ah = (__nv_bfloat16*)smem;
    __nv_bfloat16* Av = Ah + 128*ASTRA;
    float* Ps = (float*)(Av + 128*ASTRA);
    float* Pt = Ps + 256;

    const int tid  = threadIdx.x;
    const int lane = tid & 31;
    const int w    = tid >> 5;
    const int wm   = w & 3;
    const int wn   = w >> 2;
    const int n0   = blockIdx.x * 128;

    Ps[tid] = (tid < 128) ? bc1[tid] : wc2[tid - 128];

    #pragma unroll
    for (int i = 0; i < 8; i++) {
        int idx = tid + i*256;
        int m = idx >> 4, k = (idx & 15) << 3;
        int gm = n0 + m;
        uint4 zh = make_uint4(0,0,0,0), zl = zh;
        if (gm < NN) {
            zh = *(const uint4*)&g_xh[(size_t)gm*128 + k];
            zl = *(const uint4*)&g_xl[(size_t)gm*128 + k];
        }
        *(uint4*)&Ah[m*ASTRA + k] = zh;
        *(uint4*)&Av[m*ASTRA + k] = zl;
    }
    __syncthreads();

    const uint32_t sAh = smem_u32(Ah), sAv = smem_u32(Av);
    const uint32_t aOff = ((wm*32 + (lane & 15))*ASTRA + (lane >> 4)*8) * 2;
    const uint32_t* wf = g_wf + (size_t)6*8*8*2*128;

    float acc[2][8][4];
    #pragma unroll
    for (int mt = 0; mt < 2; mt++)
        #pragma unroll
        for (int nt = 0; nt < 8; nt++)
            #pragma unroll
            for (int q = 0; q < 4; q++) acc[mt][nt][q] = 0.f;

    #pragma unroll 2
    for (int ks = 0; ks < 8; ks++) {
        uint32_t ah[2][4], av[2][4];
        #pragma unroll
        for (int mt = 0; mt < 2; mt++) {
            LDSM4(ah[mt], sAh + aOff + mt*(16*ASTRA*2) + ks*32);
            LDSM4(av[mt], sAv + aOff + mt*(16*ASTRA*2) + ks*32);
        }
        #pragma unroll
        for (int p = 0; p < 4; p++) {
            int p16 = wn*4 + p;
            const uint4* bp = (const uint4*)(wf + ((ks*8 + p16)*2)*128) + lane;
            uint4 h4 = __ldg(bp);
            uint4 l4 = __ldg(bp + 32);
            uint32_t bh[4] = {h4.x, h4.y, h4.z, h4.w};
            uint32_t bv[4] = {l4.x, l4.y, l4.z, l4.w};
            MMA_BLOCK_P(acc, ah, av, bh, bv, p);
        }
    }

    const int g  = lane >> 2;
    const int c2 = (lane & 3) * 2;
    #pragma unroll
    for (int mt = 0; mt < 2; mt++) {
        #pragma unroll
        for (int rh = 0; rh < 2; rh++) {
            float s = 0.f;
            #pragma unroll
            for (int nt = 0; nt < 8; nt++) {
                int n = wn*64 + nt*8 + c2;
                s += fmaxf(acc[mt][nt][rh*2]   + Ps[n],   0.f) * Ps[128+n];
                s += fmaxf(acc[mt][nt][rh*2+1] + Ps[n+1], 0.f) * Ps[128+n+1];
            }
            s += __shfl_xor_sync(0xffffffffu, s, 1);
            s += __shfl_xor_sync(0xffffffffu, s, 2);
            if ((lane & 3) == 0)
                Pt[(wm*32 + mt*16 + rh*8 + g)*2 + wn] = s;
        }
    }
    __syncthreads();
    if (tid < 128) {
        int gm = n0 + tid;
        if (gm < NN) out1[gm] = Pt[tid*2] + Pt[tid*2+1] + bc2[0];
    }
}

// ---------------- warp-per-node softmax-aggregate, unroll-4 ------------------
__global__ void k_agg(const float* __restrict__ bias,
                      const float* __restrict__ lng, const float* __restrict__ lnb,
                      int mode)
{
    int warp = (blockIdx.x*blockDim.x + threadIdx.x) >> 5;
    if (warp >= NN) return;
    int v = warp;
    int lane = threadIdx.x & 31;
    int h = lane >> 2;

    float ax = 0.f, ay = 0.f, az = 0.f, aw = 0.f;

    #pragma unroll
    for (int r = 0; r < RR; r++) {
        int base = r*NN + v;
        int st = g_off[base], d = g_off[base+1] - st;
        if (d == 0) continue;
        float erv = __ldg(&g_er[(size_t)base*HH + h]);
        const __half* hpr = g_hp + (size_t)r*NN*DD;
        const float*  elr = g_el + (size_t)r*NN*HH;

        float nx = 0.f, ny = 0.f, nz = 0.f, nw = 0.f, den = 0.f;
        int i = 0;
        for (; i + 4 <= d; i += 4) {
            int s0 = __ldg(&g_csr[st+i]),   s1 = __ldg(&g_csr[st+i+1]);
            int s2 = __ldg(&g_csr[st+i+2]), s3 = __ldg(&g_csr[st+i+3]);
            float x0 = __ldg(&elr[(size_t)s0*HH + h]) + erv;
            float x1 = __ldg(&elr[(size_t)s1*HH + h]) + erv;
            float x2 = __ldg(&elr[(size_t)s2*HH + h]) + erv;
            float x3 = __ldg(&elr[(size_t)s3*HH + h]) + erv;
            uint2 u0 = *(const uint2*)&hpr[(size_t)s0*DD + lane*4];
            uint2 u1 = *(const uint2*)&hpr[(size_t)s1*DD + lane*4];
            uint2 u2 = *(const uint2*)&hpr[(size_t)s2*DD + lane*4];
            uint2 u3 = *(const uint2*)&hpr[(size_t)s3*DD + lane*4];
            x0 = x0 > 0.f ? x0 : NEG_SLOPE*x0;
            x1 = x1 > 0.f ? x1 : NEG_SLOPE*x1;
            x2 = x2 > 0.f ? x2 : NEG_SLOPE*x2;
            x3 = x3 > 0.f ? x3 : NEG_SLOPE*x3;
            float q0 = __expf(x0), q1 = __expf(x1), q2 = __expf(x2), q3 = __expf(x3);
            den += (q0 + q1) + (q2 + q3);
            float2 a0 = __half22float2(*(__half2*)&u0.x), b0 = __half22float2(*(__half2*)&u0.y);
            float2 a1 = __half22float2(*(__half2*)&u1.x), b1 = __half22float2(*(__half2*)&u1.y);
            float2 a2 = __half22float2(*(__half2*)&u2.x), b2 = __half22float2(*(__half2*)&u2.y);
            float2 a3 = __half22float2(*(__half2*)&u3.x), b3 = __half22float2(*(__half2*)&u3.y);
            nx += q0*a0.x + q1*a1.x + q2*a2.x + q3*a3.x;
            ny += q0*a0.y + q1*a1.y + q2*a2.y + q3*a3.y;
            nz += q0*b0.x + q1*b1.x + q2*b2.x + q3*b3.x;
            nw += q0*b0.y + q1*b1.y + q2*b2.y + q3*b3.y;
        }
        for (; i < d; i++) {
            int s0 = __ldg(&g_csr[st+i]);
            float x0 = __ldg(&elr[(size_t)s0*HH + h]) + erv;
            x0 = x0 > 0.f ? x0 : NEG_SLOPE*x0;
            float q0 = __expf(x0);
            den += q0;
            uint2 u0 = *(const uint2*)&hpr[(size_t)s0*DD + lane*4];
            float2 a0 = __half22float2(*(__half2*)&u0.x), b0 = __half22float2(*(__half2*)&u0.y);
            nx += q0*a0.x; ny += q0*a0.y; nz += q0*b0.x; nw += q0*b0.y;
        }
        float rd = 1.0f / den;
        ax += nx*rd; ay += ny*rd; az += nz*rd; aw += nw*rd;
    }

    int c = lane*4;
    ax += bias[c+0] + bias[128+c+0] + bias[256+c+0];
    ay += bias[c+1] + bias[128+c+1] + bias[256+c+1];
    az += bias[c+2] + bias[128+c+2] + bias[256+c+2];
    aw += bias[c+3] + bias[128+c+3] + bias[256+c+3];

    float o0, o1, o2, o3;
    if (mode == 0) {
        o0 = fmaxf(ax,0.f); o1 = fmaxf(ay,0.f); o2 = fmaxf(az,0.f); o3 = fmaxf(aw,0.f);
        *(float4*)&g_h1[(size_t)v*DD + c] = make_float4(o0, o1, o2, o3);
    } else {
        float4 hr = *(const float4*)&g_h1[(size_t)v*DD + c];
        ax += hr.x; ay += hr.y; az += hr.z; aw += hr.w;
        float s  = ax + ay + az + aw;
        float ss = ax*ax + ay*ay + az*az + aw*aw;
        #pragma unroll
        for (int o = 16; o; o >>= 1) {
            s  += __shfl_xor_sync(0xffffffffu, s,  o);
            ss += __shfl_xor_sync(0xffffffffu, ss, o);
        }
        float mu  = s * (1.0f/128.0f);
        float var = ss * (1.0f/128.0f) - mu*mu;
        float inv = rsqrtf(var + LN_EPS);
        o0 = (ax - mu)*inv*lng[c+0] + lnb[c+0];
        o1 = (ay - mu)*inv*lng[c+1] + lnb[c+1];
        o2 = (az - mu)*inv*lng[c+2] + lnb[c+2];
        o3 = (aw - mu)*inv*lng[c+3] + lnb[c+3];
    }
    float vv[4] = {o0, o1, o2, o3};
    __nv_bfloat16 hh[4], ll[4];
    #pragma unroll
    for (int t = 0; t < 4; t++) {
        hh[t] = __float2bfloat16(vv[t]);
        ll[t] = __float2bfloat16(vv[t] - __bfloat162float(hh[t]));
    }
    *(uint2*)&g_xh[(size_t)v*DD + c] = *(const uint2*)hh;
    *(uint2*)&g_xl[(size_t)v*DD + c] = *(const uint2*)ll;
}

// ---------------- launch ----------------
extern "C" void kernel_launch(void* const* d_in, const int* in_sizes, int n_in,
                              void* d_out, int out_size)
{
    const float* feat = (const float*)d_in[0];
    const int*   esrc = (const int*)d_in[1];
    const int*   edst = (const int*)d_in[2];
    const float* W1   = (const float*)d_in[3];
    const float* al1  = (const float*)d_in[4];
    const float* ar1  = (const float*)d_in[5];
    const float* b1   = (const float*)d_in[6];
    const float* W2   = (const float*)d_in[7];
    const float* al2  = (const float*)d_in[8];
    const float* ar2  = (const float*)d_in[9];
    const float* b2   = (const float*)d_in[10];
    const float* lng  = (const float*)d_in[11];
    const float* lnb  = (const float*)d_in[12];
    const float* Wc1  = (const float*)d_in[13];
    const float* bc1  = (const float*)d_in[14];
    const float* Wc2  = (const float*)d_in[15];
    const float* bc2  = (const float*)d_in[16];
    float* out = (float*)d_out;

    cudaFuncSetAttribute(k_proj, cudaFuncAttributeMaxDynamicSharedMemorySize, SM_PROJ);
    cudaFuncSetAttribute(k_cls,  cudaFuncAttributeMaxDynamicSharedMemorySize, SM_CLS);

    const int NB = (RN + 1023) / 1024;
    int gx = (NN + 127)/128;
    dim3 gp(gx, RR);
    int aggBlocks = (NN*32 + 255)/256;

    // launch #4 is the layer-1 projection (for ncu capture)
    k_setup<<<(NN*16 + 255)/256, 256>>>(W1, W2, Wc1, feat);                // 1
    k_count<<<(RE+255)/256, 256>>>(edst);                                  // 2
    k_scan_local<<<NB, 1024>>>();                                          // 3
    k_proj<<<gp, 256, SM_PROJ>>>(0, al1, ar1);                             // 4  <-- profiled
    k_scan_bsum<<<1, 256>>>(NB);                                           // 5
    k_scan_add<<<NB, 1024>>>();                                            // 6
    k_fill<<<(RE+255)/256, 256>>>(esrc, edst);                             // 7

    k_agg<<<aggBlocks, 256>>>(b1, nullptr, nullptr, 0);                    // 8
    k_proj<<<gp, 256, SM_PROJ>>>(3, al2, ar2);                             // 9
    k_agg<<<aggBlocks, 256>>>(b2, lng, lnb, 1);                            // 10
    k_cls<<<gx, 256, SM_CLS>>>(bc1, Wc2, bc2, out);                        // 11
}

// round 11
// speedup vs baseline: 1.0628x; 1.0628x over previous
#include <cuda_runtime.h>
#include <cuda_fp16.h>
#include <cstdint>

#define NN 50000
#define EE 400000
#define RR 3
#define DD 128
#define HH 8
#define RN (RR*NN)
#define RE (RR*EE)
#define NEG_SLOPE 0.2f
#define LN_EPS 1e-5f

// ---------------- scratch (device globals; no allocs allowed) ----------------
__device__ __align__(128) __half g_hp[(size_t)RR*NN*DD];
__device__ __align__(128) float g_el[(size_t)RN*HH];
__device__ __align__(128) float g_er[(size_t)RN*HH];
__device__ __align__(128) float g_h1[(size_t)NN*DD];
__device__ __align__(128) __half g_xh[(size_t)NN*DD];   // fp16 hi split of GEMM input
__device__ __align__(128) __half g_xl[(size_t)NN*DD];   // fp16 lo split
__device__ __align__(128) int   g_off[RN+1];
__device__ __align__(128) int   g_cnt[RN];
__device__ __align__(128) int   g_csr[RE];      // src node ids
__device__ __align__(128) int   g_bsum[256];
// pre-built B mma fragments (fp16, single split): [slot(7)][ks(8)][n16(8)][lane(32)][reg(4)]
__device__ __align__(128) uint32_t g_wf[7*8*8*32*4];

__device__ __forceinline__ uint32_t smem_u32(const void* p) {
    uint32_t a;
    asm("{ .reg .u64 t; cvta.to.shared.u64 t, %1; cvt.u32.u64 %0, t; }" : "=r"(a) : "l"(p));
    return a;
}

#define LDSM4(R, A) \
    asm volatile("ldmatrix.sync.aligned.m8n8.x4.shared.b16 {%0,%1,%2,%3}, [%4];" \
        : "=r"((R)[0]), "=r"((R)[1]), "=r"((R)[2]), "=r"((R)[3]) : "r"(A))

#define MMA(C, A, B0, B1) \
    asm volatile("mma.sync.aligned.m16n8k16.row.col.f32.f16.f16.f32 " \
        "{%0,%1,%2,%3}, {%4,%5,%6,%7}, {%8,%9}, {%0,%1,%2,%3};" \
        : "+f"((C)[0]), "+f"((C)[1]), "+f"((C)[2]), "+f"((C)[3]) \
        : "r"((A)[0]), "r"((A)[1]), "r"((A)[2]), "r"((A)[3]), "r"(B0), "r"(B1))

// 8 MMAs of one p-iteration (2 A-terms x 4 acc quads)
#define MMA_BLOCK_P(acc, ah, av, b, p) do {         \
    MMA(acc[0][2*(p)],   ah[0], b[0], b[1]);        \
    MMA(acc[0][2*(p)+1], ah[0], b[2], b[3]);        \
    MMA(acc[1][2*(p)],   ah[1], b[0], b[1]);        \
    MMA(acc[1][2*(p)+1], ah[1], b[2], b[3]);        \
    MMA(acc[0][2*(p)],   av[0], b[0], b[1]);        \
    MMA(acc[0][2*(p)+1], av[0], b[2], b[3]);        \
    MMA(acc[1][2*(p)],   av[1], b[0], b[1]);        \
    MMA(acc[1][2*(p)+1], av[1], b[2], b[3]);        \
} while (0)

__device__ __forceinline__ uint32_t pack_h2(__half a, __half b) {
    uint16_t lo = *(uint16_t*)&a, hi = *(uint16_t*)&b;
    return (uint32_t)lo | ((uint32_t)hi << 16);
}

// ---------------- setup: cnt zero + weight fragments + feat split ------------
__global__ void k_setup(const float* __restrict__ W1, const float* __restrict__ W2,
                        const float* __restrict__ Wc1, const float* __restrict__ X)
{
    int i = blockIdx.x*blockDim.x + threadIdx.x;
    if (i < RN) g_cnt[i] = 0;

    if (i < 7*8*8*32) {
        int lane = i & 31;
        int rem  = i >> 5;
        int p16  = rem & 7;  rem >>= 3;
        int ks   = rem & 7;  rem >>= 3;
        int slot = rem;
        const float* Wsrc = (slot < 3) ? W1 + (size_t)slot*16384
                          : (slot < 6) ? W2 + (size_t)(slot-3)*16384
                          : Wc1;
        uint32_t fh[4];
        #pragma unroll
        for (int j = 0; j < 4; j++) {
            int n = p16*16 + (j>>1)*8 + (lane>>2);
            int k = ks*16  + (j&1)*8  + (lane&3)*2;
            float w0 = Wsrc[(size_t)k*128 + n];
            float w1 = Wsrc[(size_t)(k+1)*128 + n];
            fh[j] = pack_h2(__float2half_rn(w0), __float2half_rn(w1));
        }
        size_t base = (((size_t)slot*8 + ks)*8 + p16)*128 + (size_t)lane*4;
        *(uint4*)&g_wf[base] = make_uint4(fh[0], fh[1], fh[2], fh[3]);
    }

    if (i < NN*16) {
        const float* xp = X + (size_t)i*8;
        float4 a = *(const float4*)xp, b = *(const float4*)(xp+4);
        float v[8] = {a.x,a.y,a.z,a.w,b.x,b.y,b.z,b.w};
        __half hh[8], ll[8];
        #pragma unroll
        for (int t = 0; t < 8; t++) {
            hh[t] = __float2half_rn(v[t]);
            ll[t] = __float2half_rn(v[t] - __half2float(hh[t]));
        }
        *(uint4*)&g_xh[(size_t)i*8] = *(const uint4*)hh;
        *(uint4*)&g_xl[(size_t)i*8] = *(const uint4*)ll;
    }
}

// ---------------- CSR build ----------------
__global__ void k_count(const int* __restrict__ edst) {
    int i = blockIdx.x*blockDim.x + threadIdx.x;
    if (i < RE) atomicAdd(&g_cnt[(i/EE)*NN + edst[i]], 1);
}
__device__ __forceinline__ int warp_incl_scan(int v) {
    int lane = threadIdx.x & 31;
    #pragma unroll
    for (int o = 1; o < 32; o <<= 1) {
        int t = __shfl_up_sync(0xffffffffu, v, o);
        if (lane >= o) v += t;
    }
    return v;
}
__global__ void k_scan_local() {
    __shared__ int ws[32];
    int i = blockIdx.x*1024 + threadIdx.x;
    int v = (i < RN) ? g_cnt[i] : 0;
    int incl = warp_incl_scan(v);
    int lane = threadIdx.x & 31, w = threadIdx.x >> 5;
    if (lane == 31) ws[w] = incl;
    __syncthreads();
    if (w == 0) { int b = ws[lane]; b = warp_incl_scan(b); ws[lane] = b; }
    __syncthreads();
    int off = (w > 0) ? ws[w-1] : 0;
    if (i < RN) g_off[i] = off + incl - v;
    if (threadIdx.x == 0) g_bsum[blockIdx.x] = ws[31];
}
__global__ void k_scan_bsum(int nb) {
    __shared__ int ws[8];
    int v = (threadIdx.x < nb) ? g_bsum[threadIdx.x] : 0;
    int incl = warp_incl_scan(v);
    int lane = threadIdx.x & 31, w = threadIdx.x >> 5;
    if (lane == 31) ws[w] = incl;
    __syncthreads();
    if (w == 0) { int b = (lane < 8) ? ws[lane] : 0; b = warp_incl_scan(b); if (lane < 8) ws[lane] = b; }
    __syncthreads();
    int off = (w > 0) ? ws[w-1] : 0;
    if (threadIdx.x < nb) g_bsum[threadIdx.x] = off + incl - v;
}
__global__ void k_scan_add() {
    int i = blockIdx.x*1024 + threadIdx.x;
    if (i < RN) {
        int o = g_off[i] + g_bsum[blockIdx.x];
        g_off[i] = o;
        g_cnt[i] = o;
    }
    if (i == 0) g_off[RN] = RE;
}
__global__ void k_fill(const int* __restrict__ esrc, const int* __restrict__ edst) {
    int i = blockIdx.x*blockDim.x + threadIdx.x;
    if (i < RE) {
        int idx = (i/EE)*NN + edst[i];
        int p = atomicAdd(&g_cnt[idx], 1);
        g_csr[p] = esrc[i];
    }
}

// ---------------- projection GEMM: fp16 2-term, coalesced epilogue ----------
#define ASTRA 136
#define SM_PROJ (2*128*ASTRA*2 + 1024)
#define SM_CLS  (2*128*ASTRA*2 + 2048)

__global__ void __launch_bounds__(256, 2)
k_proj(int slot0, const float* __restrict__ al, const float* __restrict__ ar)
{
    extern __shared__ char smem[];
    __half* Ah = (__half*)smem;                 // [128][136]
    __half* Av = Ah + 128*ASTRA;
    float* Ps = (float*)(Av + 128*ASTRA);       // 256 params, at 69632 B

    const int tid  = threadIdx.x;
    const int lane = tid & 31;
    const int w    = tid >> 5;
    const int wm   = w & 3;
    const int wn   = w >> 2;
    const int r    = blockIdx.y;
    const int slot = slot0 + r;
    const int n0   = blockIdx.x * 128;

    Ps[tid] = (tid < 128) ? al[r*128 + tid] : ar[r*128 + tid - 128];

    #pragma unroll
    for (int i = 0; i < 8; i++) {
        int idx = tid + i*256;
        int m = idx >> 4, k = (idx & 15) << 3;
        int gm = n0 + m;
        uint4 zh = make_uint4(0,0,0,0), zl = zh;
        if (gm < NN) {
            zh = *(const uint4*)&g_xh[(size_t)gm*128 + k];
            zl = *(const uint4*)&g_xl[(size_t)gm*128 + k];
        }
        *(uint4*)&Ah[m*ASTRA + k] = zh;
        *(uint4*)&Av[m*ASTRA + k] = zl;
    }
    __syncthreads();

    const uint32_t sAh = smem_u32(Ah), sAv = smem_u32(Av);
    const uint32_t aOff = ((wm*32 + (lane & 15))*ASTRA + (lane >> 4)*8) * 2;
    const uint32_t* wf = g_wf + (size_t)slot*8*8*128;

    float acc[2][8][4];
    #pragma unroll
    for (int mt = 0; mt < 2; mt++)
        #pragma unroll
        for (int nt = 0; nt < 8; nt++)
            #pragma unroll
            for (int q = 0; q < 4; q++) acc[mt][nt][q] = 0.f;

    #pragma unroll 2
    for (int ks = 0; ks < 8; ks++) {
        uint32_t ah[2][4], av[2][4];
        #pragma unroll
        for (int mt = 0; mt < 2; mt++) {
            LDSM4(ah[mt], sAh + aOff + mt*(16*ASTRA*2) + ks*32);
            LDSM4(av[mt], sAv + aOff + mt*(16*ASTRA*2) + ks*32);
        }
        #pragma unroll
        for (int p = 0; p < 4; p++) {
            int p16 = wn*4 + p;
            uint4 b4 = __ldg((const uint4*)(wf + (ks*8 + p16)*128) + lane);
            uint32_t b[4] = {b4.x, b4.y, b4.z, b4.w};
            MMA_BLOCK_P(acc, ah, av, b, p);
        }
    }

    // ---- epilogue: stage tile + el/er in smem, copy coalesced ----
    __syncthreads();                 // all LDSM reads done; A region reusable
    __half* Ts  = (__half*)smem;     // [128][136] fp16 tile (34816 B)
    float*  Els = (float*)(smem + 128*ASTRA*2);        // 128x8 (4KB)
    float*  Ers = Els + 128*8;                         // 128x8 (4KB)  (ends 43KB < Ps)

    const int g  = lane >> 2;
    const int c2 = (lane & 3) * 2;
    #pragma unroll
    for (int mt = 0; mt < 2; mt++) {
        #pragma unroll
        for (int rh = 0; rh < 2; rh++) {
            int row = wm*32 + mt*16 + rh*8 + g;
            #pragma unroll
            for (int nt = 0; nt < 8; nt++) {
                int n = wn*64 + nt*8 + c2;
                *(__half2*)&Ts[row*ASTRA + n] =
                    __floats2half2_rn(acc[mt][nt][rh*2], acc[mt][nt][rh*2+1]);
            }
            #pragma unroll
            for (int j = 0; j < 4; j++) {
                float el = 0.f, er = 0.f;
                #pragma unroll
                for (int t = 0; t < 2; t++) {
                    int nt = 2*j + t;
                    int n = wn*64 + nt*8 + c2;
                    float v0 = acc[mt][nt][rh*2], v1 = acc[mt][nt][rh*2+1];
                    el += v0*Ps[n] + v1*Ps[n+1];
                    er += v0*Ps[128+n] + v1*Ps[128+n+1];
                }
                el += __shfl_xor_sync(0xffffffffu, el, 1);
                er += __shfl_xor_sync(0xffffffffu, er, 1);
                el += __shfl_xor_sync(0xffffffffu, el, 2);
                er += __shfl_xor_sync(0xffffffffu, er, 2);
                if ((lane & 3) == 0) {
                    Els[row*8 + wn*4 + j] = el;
                    Ers[row*8 + wn*4 + j] = er;
                }
            }
        }
    }
    __syncthreads();

    // coalesced hp copy (16B chunks)
    #pragma unroll
    for (int i = 0; i < 8; i++) {
        int idx = tid + i*256;
        int row = idx >> 4, cc = idx & 15;
        int gm = n0 + row;
        if (gm < NN)
            *(uint4*)&g_hp[((size_t)r*NN + gm)*128 + cc*8] = *(const uint4*)&Ts[row*ASTRA + cc*8];
    }
    // coalesced el/er copy
    #pragma unroll
    for (int i = 0; i < 4; i++) {
        int idx = tid + i*256;
        int row = idx >> 3;
        if (n0 + row < NN) {
            g_el[((size_t)r*NN + n0)*8 + idx] = Els[idx];
            g_er[((size_t)r*NN + n0)*8 + idx] = Ers[idx];
        }
    }
}

// ---------------- classifier GEMM ----------------
__global__ void __launch_bounds__(256, 2)
k_cls(const float* __restrict__ bc1, const float* __restrict__ wc2,
      const float* __restrict__ bc2, float* __restrict__ out1)
{
    extern __shared__ char smem[];
    __half* Ah = (__half*)smem;
    __half* Av = Ah + 128*ASTRA;
    float* Ps = (float*)(Av + 128*ASTRA);
    float* Pt = Ps + 256;

    const int tid  = threadIdx.x;
    const int lane = tid & 31;
    const int w    = tid >> 5;
    const int wm   = w & 3;
    const int wn   = w >> 2;
    const int n0   = blockIdx.x * 128;

    Ps[tid] = (tid < 128) ? bc1[tid] : wc2[tid - 128];

    #pragma unroll
    for (int i = 0; i < 8; i++) {
        int idx = tid + i*256;
        int m = idx >> 4, k = (idx & 15) << 3;
        int gm = n0 + m;
        uint4 zh = make_uint4(0,0,0,0), zl = zh;
        if (gm < NN) {
            zh = *(const uint4*)&g_xh[(size_t)gm*128 + k];
            zl = *(const uint4*)&g_xl[(size_t)gm*128 + k];
        }
        *(uint4*)&Ah[m*ASTRA + k] = zh;
        *(uint4*)&Av[m*ASTRA + k] = zl;
    }
    __syncthreads();

    const uint32_t sAh = smem_u32(Ah), sAv = smem_u32(Av);
    const uint32_t aOff = ((wm*32 + (lane & 15))*ASTRA + (lane >> 4)*8) * 2;
    const uint32_t* wf = g_wf + (size_t)6*8*8*128;

    float acc[2][8][4];
    #pragma unroll
    for (int mt = 0; mt < 2; mt++)
        #pragma unroll
        for (int nt = 0; nt < 8; nt++)
            #pragma unroll
            for (int q = 0; q < 4; q++) acc[mt][nt][q] = 0.f;

    #pragma unroll 2
    for (int ks = 0; ks < 8; ks++) {
        uint32_t ah[2][4], av[2][4];
        #pragma unroll
        for (int mt = 0; mt < 2; mt++) {
            LDSM4(ah[mt], sAh + aOff + mt*(16*ASTRA*2) + ks*32);
            LDSM4(av[mt], sAv + aOff + mt*(16*ASTRA*2) + ks*32);
        }
        #pragma unroll
        for (int p = 0; p < 4; p++) {
            int p16 = wn*4 + p;
            uint4 b4 = __ldg((const uint4*)(wf + (ks*8 + p16)*128) + lane);
            uint32_t b[4] = {b4.x, b4.y, b4.z, b4.w};
            MMA_BLOCK_P(acc, ah, av, b, p);
        }
    }

    const int g  = lane >> 2;
    const int c2 = (lane & 3) * 2;
    #pragma unroll
    for (int mt = 0; mt < 2; mt++) {
        #pragma unroll
        for (int rh = 0; rh < 2; rh++) {
            float s = 0.f;
            #pragma unroll
            for (int nt = 0; nt < 8; nt++) {
                int n = wn*64 + nt*8 + c2;
                s += fmaxf(acc[mt][nt][rh*2]   + Ps[n],   0.f) * Ps[128+n];
                s += fmaxf(acc[mt][nt][rh*2+1] + Ps[n+1], 0.f) * Ps[128+n+1];
            }
            s += __shfl_xor_sync(0xffffffffu, s, 1);
            s += __shfl_xor_sync(0xffffffffu, s, 2);
            if ((lane & 3) == 0)
                Pt[(wm*32 + mt*16 + rh*8 + g)*2 + wn] = s;
        }
    }
    __syncthreads();
    if (tid < 128) {
        int gm = n0 + tid;
        if (gm < NN) out1[gm] = Pt[tid*2] + Pt[tid*2+1] + bc2[0];
    }
}

// ---------------- warp-per-node softmax-aggregate, unroll-4 ------------------
__global__ void k_agg(const float* __restrict__ bias,
                      const float* __restrict__ lng, const float* __restrict__ lnb,
                      int mode)
{
    int warp = (blockIdx.x*blockDim.x + threadIdx.x) >> 5;
    if (warp >= NN) return;
    int v = warp;
    int lane = threadIdx.x & 31;
    int h = lane >> 2;

    float ax = 0.f, ay = 0.f, az = 0.f, aw = 0.f;

    #pragma unroll
    for (int r = 0; r < RR; r++) {
        int base = r*NN + v;
        int st = g_off[base], d = g_off[base+1] - st;
        if (d == 0) continue;
        float erv = __ldg(&g_er[(size_t)base*HH + h]);
        const __half* hpr = g_hp + (size_t)r*NN*DD;
        const float*  elr = g_el + (size_t)r*NN*HH;

        float nx = 0.f, ny = 0.f, nz = 0.f, nw = 0.f, den = 0.f;
        int i = 0;
        for (; i + 4 <= d; i += 4) {
            int s0 = __ldg(&g_csr[st+i]),   s1 = __ldg(&g_csr[st+i+1]);
            int s2 = __ldg(&g_csr[st+i+2]), s3 = __ldg(&g_csr[st+i+3]);
            float x0 = __ldg(&elr[(size_t)s0*HH + h]) + erv;
            float x1 = __ldg(&elr[(size_t)s1*HH + h]) + erv;
            float x2 = __ldg(&elr[(size_t)s2*HH + h]) + erv;
            float x3 = __ldg(&elr[(size_t)s3*HH + h]) + erv;
            uint2 u0 = *(const uint2*)&hpr[(size_t)s0*DD + lane*4];
            uint2 u1 = *(const uint2*)&hpr[(size_t)s1*DD + lane*4];
            uint2 u2 = *(const uint2*)&hpr[(size_t)s2*DD + lane*4];
            uint2 u3 = *(const uint2*)&hpr[(size_t)s3*DD + lane*4];
            x0 = x0 > 0.f ? x0 : NEG_SLOPE*x0;
            x1 = x1 > 0.f ? x1 : NEG_SLOPE*x1;
            x2 = x2 > 0.f ? x2 : NEG_SLOPE*x2;
            x3 = x3 > 0.f ? x3 : NEG_SLOPE*x3;
            float q0 = __expf(x0), q1 = __expf(x1), q2 = __expf(x2), q3 = __expf(x3);
            den += (q0 + q1) + (q2 + q3);
            float2 a0 = __half22float2(*(__half2*)&u0.x), b0 = __half22float2(*(__half2*)&u0.y);
            float2 a1 = __half22float2(*(__half2*)&u1.x), b1 = __half22float2(*(__half2*)&u1.y);
            float2 a2 = __half22float2(*(__half2*)&u2.x), b2 = __half22float2(*(__half2*)&u2.y);
            float2 a3 = __half22float2(*(__half2*)&u3.x), b3 = __half22float2(*(__half2*)&u3.y);
            nx += q0*a0.x + q1*a1.x + q2*a2.x + q3*a3.x;
            ny += q0*a0.y + q1*a1.y + q2*a2.y + q3*a3.y;
            nz += q0*b0.x + q1*b1.x + q2*b2.x + q3*b3.x;
            nw += q0*b0.y + q1*b1.y + q2*b2.y + q3*b3.y;
        }
        for (; i < d; i++) {
            int s0 = __ldg(&g_csr[st+i]);
            float x0 = __ldg(&elr[(size_t)s0*HH + h]) + erv;
            x0 = x0 > 0.f ? x0 : NEG_SLOPE*x0;
            float q0 = __expf(x0);
            den += q0;
            uint2 u0 = *(const uint2*)&hpr[(size_t)s0*DD + lane*4];
            float2 a0 = __half22float2(*(__half2*)&u0.x), b0 = __half22float2(*(__half2*)&u0.y);
            nx += q0*a0.x; ny += q0*a0.y; nz += q0*b0.x; nw += q0*b0.y;
        }
        float rd = 1.0f / den;
        ax += nx*rd; ay += ny*rd; az += nz*rd; aw += nw*rd;
    }

    int c = lane*4;
    ax += bias[c+0] + bias[128+c+0] + bias[256+c+0];
    ay += bias[c+1] + bias[128+c+1] + bias[256+c+1];
    az += bias[c+2] + bias[128+c+2] + bias[256+c+2];
    aw += bias[c+3] + bias[128+c+3] + bias[256+c+3];

    float o0, o1, o2, o3;
    if (mode == 0) {
        o0 = fmaxf(ax,0.f); o1 = fmaxf(ay,0.f); o2 = fmaxf(az,0.f); o3 = fmaxf(aw,0.f);
        *(float4*)&g_h1[(size_t)v*DD + c] = make_float4(o0, o1, o2, o3);
    } else {
        float4 hr = *(const float4*)&g_h1[(size_t)v*DD + c];
        ax += hr.x; ay += hr.y; az += hr.z; aw += hr.w;
        float s  = ax + ay + az + aw;
        float ss = ax*ax + ay*ay + az*az + aw*aw;
        #pragma unroll
        for (int o = 16; o; o >>= 1) {
            s  += __shfl_xor_sync(0xffffffffu, s,  o);
            ss += __shfl_xor_sync(0xffffffffu, ss, o);
        }
        float mu  = s * (1.0f/128.0f);
        float var = ss * (1.0f/128.0f) - mu*mu;
        float inv = rsqrtf(var + LN_EPS);
        o0 = (ax - mu)*inv*lng[c+0] + lnb[c+0];
        o1 = (ay - mu)*inv*lng[c+1] + lnb[c+1];
        o2 = (az - mu)*inv*lng[c+2] + lnb[c+2];
        o3 = (aw - mu)*inv*lng[c+3] + lnb[c+3];
    }
    float vv[4] = {o0, o1, o2, o3};
    __half hh[4], ll[4];
    #pragma unroll
    for (int t = 0; t < 4; t++) {
        hh[t] = __float2half_rn(vv[t]);
        ll[t] = __float2half_rn(vv[t] - __half2float(hh[t]));
    }
    *(uint2*)&g_xh[(size_t)v*DD + c] = *(const uint2*)hh;
    *(uint2*)&g_xl[(size_t)v*DD + c] = *(const uint2*)ll;
}

// ---------------- launch ----------------
extern "C" void kernel_launch(void* const* d_in, const int* in_sizes, int n_in,
                              void* d_out, int out_size)
{
    const float* feat = (const float*)d_in[0];
    const int*   esrc = (const int*)d_in[1];
    const int*   edst = (const int*)d_in[2];
    const float* W1   = (const float*)d_in[3];
    const float* al1  = (const float*)d_in[4];
    const float* ar1  = (const float*)d_in[5];
    const float* b1   = (const float*)d_in[6];
    const float* W2   = (const float*)d_in[7];
    const float* al2  = (const float*)d_in[8];
    const float* ar2  = (const float*)d_in[9];
    const float* b2   = (const float*)d_in[10];
    const float* lng  = (const float*)d_in[11];
    const float* lnb  = (const float*)d_in[12];
    const float* Wc1  = (const float*)d_in[13];
    const float* bc1  = (const float*)d_in[14];
    const float* Wc2  = (const float*)d_in[15];
    const float* bc2  = (const float*)d_in[16];
    float* out = (float*)d_out;

    cudaFuncSetAttribute(k_proj, cudaFuncAttributeMaxDynamicSharedMemorySize, SM_PROJ);
    cudaFuncSetAttribute(k_cls,  cudaFuncAttributeMaxDynamicSharedMemorySize, SM_CLS);

    const int NB = (RN + 1023) / 1024;
    int gx = (NN + 127)/128;
    dim3 gp(gx, RR);
    int aggBlocks = (NN*32 + 255)/256;

    // launch #4 is the layer-1 projection (for ncu capture)
    k_setup<<<(NN*16 + 255)/256, 256>>>(W1, W2, Wc1, feat);                // 1
    k_count<<<(RE+255)/256, 256>>>(edst);                                  // 2
    k_scan_local<<<NB, 1024>>>();                                          // 3
    k_proj<<<gp, 256, SM_PROJ>>>(0, al1, ar1);                             // 4  <-- profiled
    k_scan_bsum<<<1, 256>>>(NB);                                           // 5
    k_scan_add<<<NB, 1024>>>();                                            // 6
    k_fill<<<(RE+255)/256, 256>>>(esrc, edst);                             // 7

    k_agg<<<aggBlocks, 256>>>(b1, nullptr, nullptr, 0);                    // 8
    k_proj<<<gp, 256, SM_PROJ>>>(3, al2, ar2);                             // 9
    k_agg<<<aggBlocks, 256>>>(b2, lng, lnb, 1);                            // 10
    k_cls<<<gx, 256, SM_CLS>>>(bc1, Wc2, bc2, out);                        // 11
}

// round 12
// speedup vs baseline: 1.1823x; 1.1125x over previous
#include <cuda_runtime.h>
#include <cuda_fp16.h>
#include <cstdint>

#define NN 50000
#define EE 400000
#define RR 3
#define DD 128
#define HH 8
#define RN (RR*NN)
#define RE (RR*EE)
#define NEG_SLOPE 0.2f
#define LN_EPS 1e-5f

// ---------------- scratch (device globals; no allocs allowed) ----------------
__device__ __align__(128) __half g_hp[(size_t)RR*NN*DD];
__device__ __align__(128) float g_el[(size_t)RN*HH];
__device__ __align__(128) float g_er[(size_t)RN*HH];
__device__ __align__(128) float g_h1[(size_t)NN*DD];
__device__ __align__(128) __half g_xh[(size_t)NN*DD];   // fp16 GEMM input
__device__ __align__(128) int   g_off[RN+1];
__device__ __align__(128) int   g_cnt[RN];
__device__ __align__(128) int   g_csr[RE];      // src node ids
__device__ __align__(128) int   g_bsum[256];
// pre-built B mma fragments (fp16): [slot(7)][ks(8)][n16(8)][lane(32)][reg(4)]
__device__ __align__(128) uint32_t g_wf[7*8*8*32*4];

__device__ __forceinline__ uint32_t smem_u32(const void* p) {
    uint32_t a;
    asm("{ .reg .u64 t; cvta.to.shared.u64 t, %1; cvt.u32.u64 %0, t; }" : "=r"(a) : "l"(p));
    return a;
}

#define LDSM4(R, A) \
    asm volatile("ldmatrix.sync.aligned.m8n8.x4.shared.b16 {%0,%1,%2,%3}, [%4];" \
        : "=r"((R)[0]), "=r"((R)[1]), "=r"((R)[2]), "=r"((R)[3]) : "r"(A))

#define MMA(C, A, B0, B1) \
    asm volatile("mma.sync.aligned.m16n8k16.row.col.f32.f16.f16.f32 " \
        "{%0,%1,%2,%3}, {%4,%5,%6,%7}, {%8,%9}, {%0,%1,%2,%3};" \
        : "+f"((C)[0]), "+f"((C)[1]), "+f"((C)[2]), "+f"((C)[3]) \
        : "r"((A)[0]), "r"((A)[1]), "r"((A)[2]), "r"((A)[3]), "r"(B0), "r"(B1))

// 4 MMAs of one p-iteration (1 A-term x 4 acc quads)
#define MMA_BLOCK_P(acc, ah, b, p) do {             \
    MMA(acc[0][2*(p)],   ah[0], b[0], b[1]);        \
    MMA(acc[0][2*(p)+1], ah[0], b[2], b[3]);        \
    MMA(acc[1][2*(p)],   ah[1], b[0], b[1]);        \
    MMA(acc[1][2*(p)+1], ah[1], b[2], b[3]);        \
} while (0)

__device__ __forceinline__ uint32_t pack_h2(__half a, __half b) {
    uint16_t lo = *(uint16_t*)&a, hi = *(uint16_t*)&b;
    return (uint32_t)lo | ((uint32_t)hi << 16);
}

// ---------------- setup: cnt zero + weight fragments + feat convert ----------
__global__ void k_setup(const float* __restrict__ W1, const float* __restrict__ W2,
                        const float* __restrict__ Wc1, const float* __restrict__ X)
{
    int i = blockIdx.x*blockDim.x + threadIdx.x;
    if (i < RN) g_cnt[i] = 0;

    if (i < 7*8*8*32) {
        int lane = i & 31;
        int rem  = i >> 5;
        int p16  = rem & 7;  rem >>= 3;
        int ks   = rem & 7;  rem >>= 3;
        int slot = rem;
        const float* Wsrc = (slot < 3) ? W1 + (size_t)slot*16384
                          : (slot < 6) ? W2 + (size_t)(slot-3)*16384
                          : Wc1;
        uint32_t fh[4];
        #pragma unroll
        for (int j = 0; j < 4; j++) {
            int n = p16*16 + (j>>1)*8 + (lane>>2);
            int k = ks*16  + (j&1)*8  + (lane&3)*2;
            float w0 = Wsrc[(size_t)k*128 + n];
            float w1 = Wsrc[(size_t)(k+1)*128 + n];
            fh[j] = pack_h2(__float2half_rn(w0), __float2half_rn(w1));
        }
        size_t base = (((size_t)slot*8 + ks)*8 + p16)*128 + (size_t)lane*4;
        *(uint4*)&g_wf[base] = make_uint4(fh[0], fh[1], fh[2], fh[3]);
    }

    if (i < NN*16) {
        const float* xp = X + (size_t)i*8;
        float4 a = *(const float4*)xp, b = *(const float4*)(xp+4);
        float v[8] = {a.x,a.y,a.z,a.w,b.x,b.y,b.z,b.w};
        __half hh[8];
        #pragma unroll
        for (int t = 0; t < 8; t++) hh[t] = __float2half_rn(v[t]);
        *(uint4*)&g_xh[(size_t)i*8] = *(const uint4*)hh;
    }
}

// ---------------- CSR build ----------------
__global__ void k_count(const int* __restrict__ edst) {
    int i = blockIdx.x*blockDim.x + threadIdx.x;
    if (i < RE) atomicAdd(&g_cnt[(i/EE)*NN + edst[i]], 1);
}
__device__ __forceinline__ int warp_incl_scan(int v) {
    int lane = threadIdx.x & 31;
    #pragma unroll
    for (int o = 1; o < 32; o <<= 1) {
        int t = __shfl_up_sync(0xffffffffu, v, o);
        if (lane >= o) v += t;
    }
    return v;
}
__global__ void k_scan_local() {
    __shared__ int ws[32];
    int i = blockIdx.x*1024 + threadIdx.x;
    int v = (i < RN) ? g_cnt[i] : 0;
    int incl = warp_incl_scan(v);
    int lane = threadIdx.x & 31, w = threadIdx.x >> 5;
    if (lane == 31) ws[w] = incl;
    __syncthreads();
    if (w == 0) { int b = ws[lane]; b = warp_incl_scan(b); ws[lane] = b; }
    __syncthreads();
    int off = (w > 0) ? ws[w-1] : 0;
    if (i < RN) g_off[i] = off + incl - v;
    if (threadIdx.x == 0) g_bsum[blockIdx.x] = ws[31];
}
__global__ void k_scan_bsum(int nb) {
    __shared__ int ws[8];
    int v = (threadIdx.x < nb) ? g_bsum[threadIdx.x] : 0;
    int incl = warp_incl_scan(v);
    int lane = threadIdx.x & 31, w = threadIdx.x >> 5;
    if (lane == 31) ws[w] = incl;
    __syncthreads();
    if (w == 0) { int b = (lane < 8) ? ws[lane] : 0; b = warp_incl_scan(b); if (lane < 8) ws[lane] = b; }
    __syncthreads();
    int off = (w > 0) ? ws[w-1] : 0;
    if (threadIdx.x < nb) g_bsum[threadIdx.x] = off + incl - v;
}
__global__ void k_scan_add() {
    int i = blockIdx.x*1024 + threadIdx.x;
    if (i < RN) {
        int o = g_off[i] + g_bsum[blockIdx.x];
        g_off[i] = o;
        g_cnt[i] = o;
    }
    if (i == 0) g_off[RN] = RE;
}
__global__ void k_fill(const int* __restrict__ esrc, const int* __restrict__ edst) {
    int i = blockIdx.x*blockDim.x + threadIdx.x;
    if (i < RE) {
        int idx = (i/EE)*NN + edst[i];
        int p = atomicAdd(&g_cnt[idx], 1);
        g_csr[p] = esrc[i];
    }
}

// ---------------- projection GEMM: fp16 single-term, coalesced epilogue ------
#define ASTRA 136
#define SM_PROJ (128*ASTRA*2 + 16*1024 + 1024)
#define SM_CLS  (128*ASTRA*2 + 2048)

__global__ void __launch_bounds__(256, 2)
k_proj(int slot0, const float* __restrict__ al, const float* __restrict__ ar)
{
    extern __shared__ char smem[];
    __half* Ah = (__half*)smem;                 // [128][136] (34816 B)
    float* Ps = (float*)(smem + 128*ASTRA*2 + 16*1024);   // 256 params

    const int tid  = threadIdx.x;
    const int lane = tid & 31;
    const int w    = tid >> 5;
    const int wm   = w & 3;
    const int wn   = w >> 2;
    const int r    = blockIdx.y;
    const int slot = slot0 + r;
    const int n0   = blockIdx.x * 128;

    Ps[tid] = (tid < 128) ? al[r*128 + tid] : ar[r*128 + tid - 128];

    #pragma unroll
    for (int i = 0; i < 4; i++) {
        int idx = tid + i*256;
        int m = idx >> 3, k = (idx & 7) << 4;
        int gm = n0 + m;
        uint4 z0 = make_uint4(0,0,0,0), z1 = z0;
        if (gm < NN) {
            z0 = *(const uint4*)&g_xh[(size_t)gm*128 + k];
            z1 = *(const uint4*)&g_xh[(size_t)gm*128 + k + 8];
        }
        *(uint4*)&Ah[m*ASTRA + k]     = z0;
        *(uint4*)&Ah[m*ASTRA + k + 8] = z1;
    }
    __syncthreads();

    const uint32_t sAh = smem_u32(Ah);
    const uint32_t aOff = ((wm*32 + (lane & 15))*ASTRA + (lane >> 4)*8) * 2;
    const uint32_t* wf = g_wf + (size_t)slot*8*8*128;

    float acc[2][8][4];
    #pragma unroll
    for (int mt = 0; mt < 2; mt++)
        #pragma unroll
        for (int nt = 0; nt < 8; nt++)
            #pragma unroll
            for (int q = 0; q < 4; q++) acc[mt][nt][q] = 0.f;

    #pragma unroll 2
    for (int ks = 0; ks < 8; ks++) {
        uint32_t ah[2][4];
        #pragma unroll
        for (int mt = 0; mt < 2; mt++)
            LDSM4(ah[mt], sAh + aOff + mt*(16*ASTRA*2) + ks*32);
        #pragma unroll
        for (int p = 0; p < 4; p++) {
            int p16 = wn*4 + p;
            uint4 b4 = __ldg((const uint4*)(wf + (ks*8 + p16)*128) + lane);
            uint32_t b[4] = {b4.x, b4.y, b4.z, b4.w};
            MMA_BLOCK_P(acc, ah, b, p);
        }
    }

    // ---- epilogue: stage tile + el/er in smem, copy coalesced ----
    __syncthreads();
    __half* Ts  = (__half*)smem;                        // [128][136]
    float*  Els = (float*)(smem + 128*ASTRA*2);         // 128x8
    float*  Ers = Els + 128*8;                          // 128x8

    const int g  = lane >> 2;
    const int c2 = (lane & 3) * 2;
    #pragma unroll
    for (int mt = 0; mt < 2; mt++) {
        #pragma unroll
        for (int rh = 0; rh < 2; rh++) {
            int row = wm*32 + mt*16 + rh*8 + g;
            #pragma unroll
            for (int nt = 0; nt < 8; nt++) {
                int n = wn*64 + nt*8 + c2;
                *(__half2*)&Ts[row*ASTRA + n] =
                    __floats2half2_rn(acc[mt][nt][rh*2], acc[mt][nt][rh*2+1]);
            }
            #pragma unroll
            for (int j = 0; j < 4; j++) {
                float el = 0.f, er = 0.f;
                #pragma unroll
                for (int t = 0; t < 2; t++) {
                    int nt = 2*j + t;
                    int n = wn*64 + nt*8 + c2;
                    float v0 = acc[mt][nt][rh*2], v1 = acc[mt][nt][rh*2+1];
                    el += v0*Ps[n] + v1*Ps[n+1];
                    er += v0*Ps[128+n] + v1*Ps[128+n+1];
                }
                el += __shfl_xor_sync(0xffffffffu, el, 1);
                er += __shfl_xor_sync(0xffffffffu, er, 1);
                el += __shfl_xor_sync(0xffffffffu, el, 2);
                er += __shfl_xor_sync(0xffffffffu, er, 2);
                if ((lane & 3) == 0) {
                    Els[row*8 + wn*4 + j] = el;
                    Ers[row*8 + wn*4 + j] = er;
                }
            }
        }
    }
    __syncthreads();

    // coalesced hp copy (16B chunks)
    #pragma unroll
    for (int i = 0; i < 8; i++) {
        int idx = tid + i*256;
        int row = idx >> 4, cc = idx & 15;
        int gm = n0 + row;
        if (gm < NN)
            *(uint4*)&g_hp[((size_t)r*NN + gm)*128 + cc*8] = *(const uint4*)&Ts[row*ASTRA + cc*8];
    }
    // coalesced el/er copy
    #pragma unroll
    for (int i = 0; i < 4; i++) {
        int idx = tid + i*256;
        int row = idx >> 3;
        if (n0 + row < NN) {
            g_el[((size_t)r*NN + n0)*8 + idx] = Els[idx];
            g_er[((size_t)r*NN + n0)*8 + idx] = Ers[idx];
        }
    }
}

// ---------------- classifier GEMM ----------------
__global__ void __launch_bounds__(256, 2)
k_cls(const float* __restrict__ bc1, const float* __restrict__ wc2,
      const float* __restrict__ bc2, float* __restrict__ out1)
{
    extern __shared__ char smem[];
    __half* Ah = (__half*)smem;
    float* Ps = (float*)(smem + 128*ASTRA*2);
    float* Pt = Ps + 256;

    const int tid  = threadIdx.x;
    const int lane = tid & 31;
    const int w    = tid >> 5;
    const int wm   = w & 3;
    const int wn   = w >> 2;
    const int n0   = blockIdx.x * 128;

    Ps[tid] = (tid < 128) ? bc1[tid] : wc2[tid - 128];

    #pragma unroll
    for (int i = 0; i < 4; i++) {
        int idx = tid + i*256;
        int m = idx >> 3, k = (idx & 7) << 4;
        int gm = n0 + m;
        uint4 z0 = make_uint4(0,0,0,0), z1 = z0;
        if (gm < NN) {
            z0 = *(const uint4*)&g_xh[(size_t)gm*128 + k];
            z1 = *(const uint4*)&g_xh[(size_t)gm*128 + k + 8];
        }
        *(uint4*)&Ah[m*ASTRA + k]     = z0;
        *(uint4*)&Ah[m*ASTRA + k + 8] = z1;
    }
    __syncthreads();

    const uint32_t sAh = smem_u32(Ah);
    const uint32_t aOff = ((wm*32 + (lane & 15))*ASTRA + (lane >> 4)*8) * 2;
    const uint32_t* wf = g_wf + (size_t)6*8*8*128;

    float acc[2][8][4];
    #pragma unroll
    for (int mt = 0; mt < 2; mt++)
        #pragma unroll
        for (int nt = 0; nt < 8; nt++)
            #pragma unroll
            for (int q = 0; q < 4; q++) acc[mt][nt][q] = 0.f;

    #pragma unroll 2
    for (int ks = 0; ks < 8; ks++) {
        uint32_t ah[2][4];
        #pragma unroll
        for (int mt = 0; mt < 2; mt++)
            LDSM4(ah[mt], sAh + aOff + mt*(16*ASTRA*2) + ks*32);
        #pragma unroll
        for (int p = 0; p < 4; p++) {
            int p16 = wn*4 + p;
            uint4 b4 = __ldg((const uint4*)(wf + (ks*8 + p16)*128) + lane);
            uint32_t b[4] = {b4.x, b4.y, b4.z, b4.w};
            MMA_BLOCK_P(acc, ah, b, p);
        }
    }

    const int g  = lane >> 2;
    const int c2 = (lane & 3) * 2;
    #pragma unroll
    for (int mt = 0; mt < 2; mt++) {
        #pragma unroll
        for (int rh = 0; rh < 2; rh++) {
            float s = 0.f;
            #pragma unroll
            for (int nt = 0; nt < 8; nt++) {
                int n = wn*64 + nt*8 + c2;
                s += fmaxf(acc[mt][nt][rh*2]   + Ps[n],   0.f) * Ps[128+n];
                s += fmaxf(acc[mt][nt][rh*2+1] + Ps[n+1], 0.f) * Ps[128+n+1];
            }
            s += __shfl_xor_sync(0xffffffffu, s, 1);
            s += __shfl_xor_sync(0xffffffffu, s, 2);
            if ((lane & 3) == 0)
                Pt[(wm*32 + mt*16 + rh*8 + g)*2 + wn] = s;
        }
    }
    __syncthreads();
    if (tid < 128) {
        int gm = n0 + tid;
        if (gm < NN) out1[gm] = Pt[tid*2] + Pt[tid*2+1] + bc2[0];
    }
}

// ---------------- warp-per-node softmax-aggregate, unroll-4 ------------------
__global__ void k_agg(const float* __restrict__ bias,
                      const float* __restrict__ lng, const float* __restrict__ lnb,
                      int mode)
{
    int warp = (blockIdx.x*blockDim.x + threadIdx.x) >> 5;
    if (warp >= NN) return;
    int v = warp;
    int lane = threadIdx.x & 31;
    int h = lane >> 2;

    float ax = 0.f, ay = 0.f, az = 0.f, aw = 0.f;

    #pragma unroll
    for (int r = 0; r < RR; r++) {
        int base = r*NN + v;
        int st = g_off[base], d = g_off[base+1] - st;
        if (d == 0) continue;
        float erv = __ldg(&g_er[(size_t)base*HH + h]);
        const __half* hpr = g_hp + (size_t)r*NN*DD;
        const float*  elr = g_el + (size_t)r*NN*HH;

        float nx = 0.f, ny = 0.f, nz = 0.f, nw = 0.f, den = 0.f;
        int i = 0;
        for (; i + 4 <= d; i += 4) {
            int s0 = __ldg(&g_csr[st+i]),   s1 = __ldg(&g_csr[st+i+1]);
            int s2 = __ldg(&g_csr[st+i+2]), s3 = __ldg(&g_csr[st+i+3]);
            float x0 = __ldg(&elr[(size_t)s0*HH + h]) + erv;
            float x1 = __ldg(&elr[(size_t)s1*HH + h]) + erv;
            float x2 = __ldg(&elr[(size_t)s2*HH + h]) + erv;
            float x3 = __ldg(&elr[(size_t)s3*HH + h]) + erv;
            uint2 u0 = *(const uint2*)&hpr[(size_t)s0*DD + lane*4];
            uint2 u1 = *(const uint2*)&hpr[(size_t)s1*DD + lane*4];
            uint2 u2 = *(const uint2*)&hpr[(size_t)s2*DD + lane*4];
            uint2 u3 = *(const uint2*)&hpr[(size_t)s3*DD + lane*4];
            x0 = x0 > 0.f ? x0 : NEG_SLOPE*x0;
            x1 = x1 > 0.f ? x1 : NEG_SLOPE*x1;
            x2 = x2 > 0.f ? x2 : NEG_SLOPE*x2;
            x3 = x3 > 0.f ? x3 : NEG_SLOPE*x3;
            float q0 = __expf(x0), q1 = __expf(x1), q2 = __expf(x2), q3 = __expf(x3);
            den += (q0 + q1) + (q2 + q3);
            float2 a0 = __half22float2(*(__half2*)&u0.x), b0 = __half22float2(*(__half2*)&u0.y);
            float2 a1 = __half22float2(*(__half2*)&u1.x), b1 = __half22float2(*(__half2*)&u1.y);
            float2 a2 = __half22float2(*(__half2*)&u2.x), b2 = __half22float2(*(__half2*)&u2.y);
            float2 a3 = __half22float2(*(__half2*)&u3.x), b3 = __half22float2(*(__half2*)&u3.y);
            nx += q0*a0.x + q1*a1.x + q2*a2.x + q3*a3.x;
            ny += q0*a0.y + q1*a1.y + q2*a2.y + q3*a3.y;
            nz += q0*b0.x + q1*b1.x + q2*b2.x + q3*b3.x;
            nw += q0*b0.y + q1*b1.y + q2*b2.y + q3*b3.y;
        }
        for (; i < d; i++) {
            int s0 = __ldg(&g_csr[st+i]);
            float x0 = __ldg(&elr[(size_t)s0*HH + h]) + erv;
            x0 = x0 > 0.f ? x0 : NEG_SLOPE*x0;
            float q0 = __expf(x0);
            den += q0;
            uint2 u0 = *(const uint2*)&hpr[(size_t)s0*DD + lane*4];
            float2 a0 = __half22float2(*(__half2*)&u0.x), b0 = __half22float2(*(__half2*)&u0.y);
            nx += q0*a0.x; ny += q0*a0.y; nz += q0*b0.x; nw += q0*b0.y;
        }
        float rd = 1.0f / den;
        ax += nx*rd; ay += ny*rd; az += nz*rd; aw += nw*rd;
    }

    int c = lane*4;
    ax += bias[c+0] + bias[128+c+0] + bias[256+c+0];
    ay += bias[c+1] + bias[128+c+1] + bias[256+c+1];
    az += bias[c+2] + bias[128+c+2] + bias[256+c+2];
    aw += bias[c+3] + bias[128+c+3] + bias[256+c+3];

    float o0, o1, o2, o3;
    if (mode == 0) {
        o0 = fmaxf(ax,0.f); o1 = fmaxf(ay,0.f); o2 = fmaxf(az,0.f); o3 = fmaxf(aw,0.f);
        *(float4*)&g_h1[(size_t)v*DD + c] = make_float4(o0, o1, o2, o3);
    } else {
        float4 hr = *(const float4*)&g_h1[(size_t)v*DD + c];
        ax += hr.x; ay += hr.y; az += hr.z; aw += hr.w;
        float s  = ax + ay + az + aw;
        float ss = ax*ax + ay*ay + az*az + aw*aw;
        #pragma unroll
        for (int o = 16; o; o >>= 1) {
            s  += __shfl_xor_sync(0xffffffffu, s,  o);
            ss += __shfl_xor_sync(0xffffffffu, ss, o);
        }
        float mu  = s * (1.0f/128.0f);
        float var = ss * (1.0f/128.0f) - mu*mu;
        float inv = rsqrtf(var + LN_EPS);
        o0 = (ax - mu)*inv*lng[c+0] + lnb[c+0];
        o1 = (ay - mu)*inv*lng[c+1] + lnb[c+1];
        o2 = (az - mu)*inv*lng[c+2] + lnb[c+2];
        o3 = (aw - mu)*inv*lng[c+3] + lnb[c+3];
    }
    __half hh[4] = {__float2half_rn(o0), __float2half_rn(o1),
                    __float2half_rn(o2), __float2half_rn(o3)};
    *(uint2*)&g_xh[(size_t)v*DD + c] = *(const uint2*)hh;
}

// ---------------- launch ----------------
extern "C" void kernel_launch(void* const* d_in, const int* in_sizes, int n_in,
                              void* d_out, int out_size)
{
    const float* feat = (const float*)d_in[0];
    const int*   esrc = (const int*)d_in[1];
    const int*   edst = (const int*)d_in[2];
    const float* W1   = (const float*)d_in[3];
    const float* al1  = (const float*)d_in[4];
    const float* ar1  = (const float*)d_in[5];
    const float* b1   = (const float*)d_in[6];
    const float* W2   = (const float*)d_in[7];
    const float* al2  = (const float*)d_in[8];
    const float* ar2  = (const float*)d_in[9];
    const float* b2   = (const float*)d_in[10];
    const float* lng  = (const float*)d_in[11];
    const float* lnb  = (const float*)d_in[12];
    const float* Wc1  = (const float*)d_in[13];
    const float* bc1  = (const float*)d_in[14];
    const float* Wc2  = (const float*)d_in[15];
    const float* bc2  = (const float*)d_in[16];
    float* out = (float*)d_out;

    cudaFuncSetAttribute(k_proj, cudaFuncAttributeMaxDynamicSharedMemorySize, SM_PROJ);
    cudaFuncSetAttribute(k_cls,  cudaFuncAttributeMaxDynamicSharedMemorySize, SM_CLS);

    const int NB = (RN + 1023) / 1024;
    int gx = (NN + 127)/128;
    dim3 gp(gx, RR);
    int aggBlocks = (NN*32 + 255)/256;

    // launch #4 is the layer-1 projection (for ncu capture)
    k_setup<<<(NN*16 + 255)/256, 256>>>(W1, W2, Wc1, feat);                // 1
    k_count<<<(RE+255)/256, 256>>>(edst);                                  // 2
    k_scan_local<<<NB, 1024>>>();                                          // 3
    k_proj<<<gp, 256, SM_PROJ>>>(0, al1, ar1);                             // 4  <-- profiled
    k_scan_bsum<<<1, 256>>>(NB);                                           // 5
    k_scan_add<<<NB, 1024>>>();                                            // 6
    k_fill<<<(RE+255)/256, 256>>>(esrc, edst);                             // 7

    k_agg<<<aggBlocks, 256>>>(b1, nullptr, nullptr, 0);                    // 8
    k_proj<<<gp, 256, SM_PROJ>>>(3, al2, ar2);                             // 9
    k_agg<<<aggBlocks, 256>>>(b2, lng, lnb, 1);                            // 10
    k_cls<<<gx, 256, SM_CLS>>>(bc1, Wc2, bc2, out);                        // 11
}